// round 7
// baseline (speedup 1.0000x reference)
#include <cuda_runtime.h>

// ApplyDF: complex order-5 time-FIR on first 96 of 481 freq bins, copy the rest.
// spec:  [B=32][1][T=2000][F=481][2]  float32
// coefs: [B=32][ORDER=5][T=2000][NB=96][2] float32
// out:   same shape as spec
//
// TS=4 time steps per thread, all 28 loads front-batched (regs ~64),
// 256-thread blocks with __launch_bounds__(256,4) -> 1024 resident threads/SM.
// Streaming cache hints: coefs via __ldcs (zero reuse), out via __stcs
// (evict-first) so L2 is reserved for the spec taps that have 5x reuse.
//
// All indexing 32-bit (max byte offset ~246 MB < 2^31).

#define BB 32
#define TT 2000
#define FF 481
#define NB 96
#define ORD 5

__device__ __forceinline__ void cmac(float2 s, float2 c, float& r, float& i) {
    r = fmaf(s.x, c.x, fmaf(-s.y, c.y, r));
    i = fmaf(s.x, c.y, fmaf( s.y, c.x, i));
}

__global__ __launch_bounds__(256, 4) void apply_df_kernel(
    const float2* __restrict__ spec,
    const float2* __restrict__ coefs,
    float2* __restrict__ out)
{
    const int f = blockIdx.x * 256 + threadIdx.x;
    if (f >= FF) return;
    const int t0 = blockIdx.y * 4;          // TT divisible by 4
    const int b  = blockIdx.z;

    const int base0 = (b * TT + t0) * FF + f;   // float2 element index @ t0

    // Current + future taps (t0..t0+3): always in range.
    const float2 sA = __ldg(&spec[base0]);
    const float2 sB = __ldg(&spec[base0 + FF]);
    const float2 sC = __ldg(&spec[base0 + 2 * FF]);
    const float2 sD = __ldg(&spec[base0 + 3 * FF]);

    if (f >= NB) {
        __stcs(&out[base0],          sA);
        __stcs(&out[base0 + FF],     sB);
        __stcs(&out[base0 + 2 * FF], sC);
        __stcs(&out[base0 + 3 * FF], sD);
        return;
    }

    const float2 z = make_float2(0.f, 0.f);
    // History taps t0-4 .. t0-1 (zero-padded at sequence start; only t0==0 pads)
    const float2 sm4 = (t0 >= 4) ? __ldg(&spec[base0 - 4 * FF]) : z;
    const float2 sm3 = (t0 >= 3) ? __ldg(&spec[base0 - 3 * FF]) : z;
    const float2 sm2 = (t0 >= 2) ? __ldg(&spec[base0 - 2 * FF]) : z;
    const float2 sm1 = (t0 >= 1) ? __ldg(&spec[base0 - 1 * FF]) : z;

    // coefs element index for (b, n, t, f): ((b*5 + n)*TT + t)*NB + f
    const int cb   = ((b * ORD) * TT + t0) * NB + f;   // (b, n=0, t0, f)
    const int cstr = TT * NB;                          // tap-n stride; t stride = NB

    // ---- Front-batch ALL 20 coef loads before any FMA (streaming policy) ----
    const float2 c00 = __ldcs(&coefs[cb]);
    const float2 c01 = __ldcs(&coefs[cb + NB]);
    const float2 c02 = __ldcs(&coefs[cb + 2 * NB]);
    const float2 c03 = __ldcs(&coefs[cb + 3 * NB]);
    const float2 c10 = __ldcs(&coefs[cb + cstr]);
    const float2 c11 = __ldcs(&coefs[cb + cstr + NB]);
    const float2 c12 = __ldcs(&coefs[cb + cstr + 2 * NB]);
    const float2 c13 = __ldcs(&coefs[cb + cstr + 3 * NB]);
    const float2 c20 = __ldcs(&coefs[cb + 2 * cstr]);
    const float2 c21 = __ldcs(&coefs[cb + 2 * cstr + NB]);
    const float2 c22 = __ldcs(&coefs[cb + 2 * cstr + 2 * NB]);
    const float2 c23 = __ldcs(&coefs[cb + 2 * cstr + 3 * NB]);
    const float2 c30 = __ldcs(&coefs[cb + 3 * cstr]);
    const float2 c31 = __ldcs(&coefs[cb + 3 * cstr + NB]);
    const float2 c32 = __ldcs(&coefs[cb + 3 * cstr + 2 * NB]);
    const float2 c33 = __ldcs(&coefs[cb + 3 * cstr + 3 * NB]);
    const float2 c40 = __ldcs(&coefs[cb + 4 * cstr]);
    const float2 c41 = __ldcs(&coefs[cb + 4 * cstr + NB]);
    const float2 c42 = __ldcs(&coefs[cb + 4 * cstr + 2 * NB]);
    const float2 c43 = __ldcs(&coefs[cb + 4 * cstr + 3 * NB]);

    float r0 = 0.f, i0 = 0.f, r1 = 0.f, i1 = 0.f;
    float r2 = 0.f, i2 = 0.f, r3 = 0.f, i3 = 0.f;

    // out[t0+j] = sum_n spec[t0+j+n-4] * coef(t0+j, n)
    cmac(sm4, c00, r0, i0);  cmac(sm3, c10, r0, i0);  cmac(sm2, c20, r0, i0);
    cmac(sm1, c30, r0, i0);  cmac(sA,  c40, r0, i0);

    cmac(sm3, c01, r1, i1);  cmac(sm2, c11, r1, i1);  cmac(sm1, c21, r1, i1);
    cmac(sA,  c31, r1, i1);  cmac(sB,  c41, r1, i1);

    cmac(sm2, c02, r2, i2);  cmac(sm1, c12, r2, i2);  cmac(sA,  c22, r2, i2);
    cmac(sB,  c32, r2, i2);  cmac(sC,  c42, r2, i2);

    cmac(sm1, c03, r3, i3);  cmac(sA,  c13, r3, i3);  cmac(sB,  c23, r3, i3);
    cmac(sC,  c33, r3, i3);  cmac(sD,  c43, r3, i3);

    __stcs(&out[base0],          make_float2(r0, i0));
    __stcs(&out[base0 + FF],     make_float2(r1, i1));
    __stcs(&out[base0 + 2 * FF], make_float2(r2, i2));
    __stcs(&out[base0 + 3 * FF], make_float2(r3, i3));
}

extern "C" void kernel_launch(void* const* d_in, const int* in_sizes, int n_in,
                              void* d_out, int out_size)
{
    const float2* spec  = (const float2*)d_in[0];
    const float2* coefs = (const float2*)d_in[1];
    float2* out = (float2*)d_out;

    dim3 block(256, 1, 1);
    dim3 grid((FF + 255) / 256, TT / 4, BB);   // (2, 500, 32)
    apply_df_kernel<<<grid, block>>>(spec, coefs, out);
}

// round 8
// speedup vs baseline: 1.0207x; 1.0207x over previous
#include <cuda_runtime.h>

// ApplyDF: complex order-5 time-FIR on first 96 of 481 freq bins, copy the rest.
// spec:  [B=32][1][T=2000][F=481][2]  float32
// coefs: [B=32][ORDER=5][T=2000][NB=96][2] float32
// out:   same shape as spec
//
// R6 configuration (best measured): TS=4 time steps per thread, all 28 loads
// front-batched, 128-thread blocks, default cache policy. One change:
// __launch_bounds__(128, 8) -> reg cap exactly 64 (what ptxas used anyway),
// residency cap 1024 threads/SM (50%) instead of 896 (43.75%).
//
// All indexing 32-bit (max byte offset ~246 MB < 2^31).

#define BB 32
#define TT 2000
#define FF 481
#define NB 96
#define ORD 5

__device__ __forceinline__ void cmac(float2 s, float2 c, float& r, float& i) {
    r = fmaf(s.x, c.x, fmaf(-s.y, c.y, r));
    i = fmaf(s.x, c.y, fmaf( s.y, c.x, i));
}

__global__ __launch_bounds__(128, 8) void apply_df_kernel(
    const float2* __restrict__ spec,
    const float2* __restrict__ coefs,
    float2* __restrict__ out)
{
    const int f = blockIdx.x * 128 + threadIdx.x;
    if (f >= FF) return;
    const int t0 = blockIdx.y * 4;          // TT divisible by 4
    const int b  = blockIdx.z;

    const int base0 = (b * TT + t0) * FF + f;   // float2 element index @ t0

    // Current + future taps (t0..t0+3): always in range.
    const float2 sA = __ldg(&spec[base0]);
    const float2 sB = __ldg(&spec[base0 + FF]);
    const float2 sC = __ldg(&spec[base0 + 2 * FF]);
    const float2 sD = __ldg(&spec[base0 + 3 * FF]);

    if (f >= NB) {
        out[base0]          = sA;
        out[base0 + FF]     = sB;
        out[base0 + 2 * FF] = sC;
        out[base0 + 3 * FF] = sD;
        return;
    }

    const float2 z = make_float2(0.f, 0.f);
    // History taps t0-4 .. t0-1 (zero-padded at sequence start; only t0==0 pads)
    const float2 sm4 = (t0 >= 4) ? __ldg(&spec[base0 - 4 * FF]) : z;
    const float2 sm3 = (t0 >= 3) ? __ldg(&spec[base0 - 3 * FF]) : z;
    const float2 sm2 = (t0 >= 2) ? __ldg(&spec[base0 - 2 * FF]) : z;
    const float2 sm1 = (t0 >= 1) ? __ldg(&spec[base0 - 1 * FF]) : z;

    // coefs element index for (b, n, t, f): ((b*5 + n)*TT + t)*NB + f
    const int cb   = ((b * ORD) * TT + t0) * NB + f;   // (b, n=0, t0, f)
    const int cstr = TT * NB;                          // tap-n stride; t stride = NB

    // ---- Front-batch ALL 20 coef loads before any FMA ----
    const float2 c00 = __ldg(&coefs[cb]);
    const float2 c01 = __ldg(&coefs[cb + NB]);
    const float2 c02 = __ldg(&coefs[cb + 2 * NB]);
    const float2 c03 = __ldg(&coefs[cb + 3 * NB]);
    const float2 c10 = __ldg(&coefs[cb + cstr]);
    const float2 c11 = __ldg(&coefs[cb + cstr + NB]);
    const float2 c12 = __ldg(&coefs[cb + cstr + 2 * NB]);
    const float2 c13 = __ldg(&coefs[cb + cstr + 3 * NB]);
    const float2 c20 = __ldg(&coefs[cb + 2 * cstr]);
    const float2 c21 = __ldg(&coefs[cb + 2 * cstr + NB]);
    const float2 c22 = __ldg(&coefs[cb + 2 * cstr + 2 * NB]);
    const float2 c23 = __ldg(&coefs[cb + 2 * cstr + 3 * NB]);
    const float2 c30 = __ldg(&coefs[cb + 3 * cstr]);
    const float2 c31 = __ldg(&coefs[cb + 3 * cstr + NB]);
    const float2 c32 = __ldg(&coefs[cb + 3 * cstr + 2 * NB]);
    const float2 c33 = __ldg(&coefs[cb + 3 * cstr + 3 * NB]);
    const float2 c40 = __ldg(&coefs[cb + 4 * cstr]);
    const float2 c41 = __ldg(&coefs[cb + 4 * cstr + NB]);
    const float2 c42 = __ldg(&coefs[cb + 4 * cstr + 2 * NB]);
    const float2 c43 = __ldg(&coefs[cb + 4 * cstr + 3 * NB]);

    float r0 = 0.f, i0 = 0.f, r1 = 0.f, i1 = 0.f;
    float r2 = 0.f, i2 = 0.f, r3 = 0.f, i3 = 0.f;

    // out[t0+j] = sum_n spec[t0+j+n-4] * coef(t0+j, n)
    cmac(sm4, c00, r0, i0);  cmac(sm3, c10, r0, i0);  cmac(sm2, c20, r0, i0);
    cmac(sm1, c30, r0, i0);  cmac(sA,  c40, r0, i0);

    cmac(sm3, c01, r1, i1);  cmac(sm2, c11, r1, i1);  cmac(sm1, c21, r1, i1);
    cmac(sA,  c31, r1, i1);  cmac(sB,  c41, r1, i1);

    cmac(sm2, c02, r2, i2);  cmac(sm1, c12, r2, i2);  cmac(sA,  c22, r2, i2);
    cmac(sB,  c32, r2, i2);  cmac(sC,  c42, r2, i2);

    cmac(sm1, c03, r3, i3);  cmac(sA,  c13, r3, i3);  cmac(sB,  c23, r3, i3);
    cmac(sC,  c33, r3, i3);  cmac(sD,  c43, r3, i3);

    out[base0]          = make_float2(r0, i0);
    out[base0 + FF]     = make_float2(r1, i1);
    out[base0 + 2 * FF] = make_float2(r2, i2);
    out[base0 + 3 * FF] = make_float2(r3, i3);
}

extern "C" void kernel_launch(void* const* d_in, const int* in_sizes, int n_in,
                              void* d_out, int out_size)
{
    const float2* spec  = (const float2*)d_in[0];
    const float2* coefs = (const float2*)d_in[1];
    float2* out = (float2*)d_out;

    dim3 block(128, 1, 1);
    dim3 grid((FF + 127) / 128, TT / 4, BB);   // (4, 500, 32)
    apply_df_kernel<<<grid, block>>>(spec, coefs, out);
}